// round 15
// baseline (speedup 1.0000x reference)
#include <cuda_runtime.h>
#include <cuda_bf16.h>
#include <stdint.h>
#include <math.h>

typedef __nv_bfloat16 bf16;

#define Bc   8
#define Sc   1024
#define Hc   1024
#define NHc  16
#define DHc  64
#define MLPc 4096
#define MROWS (Bc*Sc)   // 8192

// ---------------- device scratch ----------------
__device__ bf16  g_wqT[3*Hc*Hc];         // [3072,1024] (N,K)
__device__ bf16  g_woT[Hc*Hc];           // [1024,1024]
__device__ bf16  g_w1T[(size_t)MLPc*Hc]; // [4096,1024]
__device__ bf16  g_w2T[(size_t)Hc*MLPc]; // [1024,4096]
__device__ float g_cm[Bc*6*Hc];
__device__ bf16  g_xmod[MROWS*Hc];
__device__ bf16  g_q[Bc*NHc*Sc*DHc];
__device__ bf16  g_k[Bc*NHc*Sc*DHc];
__device__ bf16  g_v[Bc*NHc*Sc*DHc];
__device__ bf16  g_y[MROWS*Hc];
__device__ float g_xres[MROWS*Hc];
__device__ bf16  g_h[(size_t)MROWS*MLPc];
__device__ float g_acc[8];
__device__ int   g_pos[MLPc];

// ---------------- low-level helpers ----------------
__device__ __forceinline__ uint32_t smem_u32(const void* p) {
    uint32_t a;
    asm("{ .reg .u64 t; cvta.to.shared.u64 t, %1; cvt.u32.u64 %0, t; }" : "=r"(a) : "l"(p));
    return a;
}
__device__ __forceinline__ void cp_async16(uint32_t s, const void* g) {
    asm volatile("cp.async.cg.shared.global [%0], [%1], 16;" :: "r"(s), "l"(g));
}
#define CP_COMMIT asm volatile("cp.async.commit_group;" ::: "memory")
#define CP_WAIT1  asm volatile("cp.async.wait_group 1;" ::: "memory")
#define CP_WAIT0  asm volatile("cp.async.wait_group 0;" ::: "memory")

__device__ __forceinline__ uint32_t sw_addr(uint32_t base, int row, int chunk) {
    return base + row * 128 + (((chunk) ^ (row & 7)) << 4);
}
__device__ __forceinline__ void ldsm4(uint32_t r[4], uint32_t a) {
    asm volatile("ldmatrix.sync.aligned.m8n8.x4.shared.b16 {%0,%1,%2,%3}, [%4];"
                 : "=r"(r[0]), "=r"(r[1]), "=r"(r[2]), "=r"(r[3]) : "r"(a));
}
__device__ __forceinline__ void ldsm4t(uint32_t r[4], uint32_t a) {
    asm volatile("ldmatrix.sync.aligned.m8n8.x4.trans.shared.b16 {%0,%1,%2,%3}, [%4];"
                 : "=r"(r[0]), "=r"(r[1]), "=r"(r[2]), "=r"(r[3]) : "r"(a));
}
__device__ __forceinline__ void mma16816(float c[4], const uint32_t a[4],
                                         uint32_t b0, uint32_t b1) {
    asm volatile(
        "mma.sync.aligned.m16n8k16.row.col.f32.bf16.bf16.f32 "
        "{%0,%1,%2,%3},{%4,%5,%6,%7},{%8,%9},{%0,%1,%2,%3};\n"
        : "+f"(c[0]), "+f"(c[1]), "+f"(c[2]), "+f"(c[3])
        : "r"(a[0]), "r"(a[1]), "r"(a[2]), "r"(a[3]), "r"(b0), "r"(b1));
}
__device__ __forceinline__ uint32_t pack_bf162(float x, float y) {
    __nv_bfloat162 h = __floats2bfloat162_rn(x, y);
    return *(uint32_t*)&h;
}
__device__ __forceinline__ float warp_sum32(float v) {
    #pragma unroll
    for (int o = 16; o > 0; o >>= 1) v += __shfl_xor_sync(0xffffffffu, v, o);
    return v;
}
__device__ __forceinline__ float block_sum256(float v, float* sm8) {
    #pragma unroll
    for (int o = 16; o > 0; o >>= 1) v += __shfl_xor_sync(0xffffffffu, v, o);
    __syncthreads();
    if ((threadIdx.x & 31) == 0) sm8[threadIdx.x >> 5] = v;
    __syncthreads();
    float r = 0.f;
    #pragma unroll
    for (int i = 0; i < 8; i++) r += sm8[i];
    return r;
}

// ---------------- fused prep: 4 weight transposes + zeroing, one launch ----------------
__global__ void k_prep(const float* __restrict__ wq, const float* __restrict__ wo,
                       const float* __restrict__ w1, const float* __restrict__ w2) {
    int id = blockIdx.x;
    if (id >= 12288) {
        int i = (id - 12288) * 256 + threadIdx.x;
        if (i < Bc * 6 * Hc) g_cm[i] = 0.f;
        if (i < MLPc) g_pos[i] = 0;
        if (i < 8)    g_acc[i] = 0.f;
        return;
    }
    const float* src; bf16* dst; int R, C, cb, rb;
    if (id < 3072)      { int t = id;        src = wq; dst = g_wqT; R = Hc;   C = 3*Hc; cb = (t % 96)  * 32; rb = (t / 96)  * 32; }
    else if (id < 4096) { int t = id - 3072; src = wo; dst = g_woT; R = Hc;   C = Hc;   cb = (t % 32)  * 32; rb = (t / 32)  * 32; }
    else if (id < 8192) { int t = id - 4096; src = w1; dst = g_w1T; R = Hc;   C = MLPc; cb = (t % 128) * 32; rb = (t / 128) * 32; }
    else                { int t = id - 8192; src = w2; dst = g_w2T; R = MLPc; C = Hc;   cb = (t % 32)  * 32; rb = (t / 32)  * 32; }
    __shared__ float t[32][33];
    int tx = threadIdx.x & 31, ty = threadIdx.x >> 5;
    #pragma unroll
    for (int i = 0; i < 32; i += 8)
        t[ty + i][tx] = src[(size_t)(rb + ty + i) * C + cb + tx];
    __syncthreads();
    #pragma unroll
    for (int i = 0; i < 32; i += 8)
        dst[(size_t)(cb + ty + i) * R + rb + tx] = __float2bfloat16(t[tx][ty + i]);
}

// split-K conditioning GEMM
__global__ void k_cond(const float* __restrict__ c, const float* __restrict__ w) {
    __shared__ float ssil[Bc * 128];
    int tid = threadIdx.x;
    int kb = blockIdx.y * 128;
    for (int i = tid; i < Bc * 128; i += 256) {
        int b = i >> 7, k = i & 127;
        float v = c[b * Hc + kb + k];
        ssil[i] = v / (1.f + expf(-v));
    }
    __syncthreads();
    int j = blockIdx.x * 256 + tid;
    float acc[Bc];
    #pragma unroll
    for (int b = 0; b < Bc; b++) acc[b] = 0.f;
    for (int k = 0; k < 128; k++) {
        float wv = w[(size_t)(kb + k) * (6 * Hc) + j];
        #pragma unroll
        for (int b = 0; b < Bc; b++) acc[b] += ssil[b * 128 + k] * wv;
    }
    #pragma unroll
    for (int b = 0; b < Bc; b++) atomicAdd(&g_cm[b * 6 * Hc + j], acc[b]);
}

// Warp-per-row LayerNorm + adaLN modulate -> bf16 (validated R10)
__global__ void __launch_bounds__(256) k_ln_w(const float* __restrict__ xp,
                                              int use_xres, int so, int sco, int acc_idx) {
    __shared__ float sm8[8];
    const float* xin = use_xres ? g_xres : xp;
    const int w = threadIdx.x >> 5, lane = threadIdx.x & 31;
    const int row = blockIdx.x * 8 + w;
    const int b = row >> 10;
    const float* xr = xin + (size_t)row * Hc;
    float4 v[8];
    #pragma unroll
    for (int j = 0; j < 8; j++) v[j] = *(const float4*)(xr + j * 128 + lane * 4);
    float s = 0.f, q = 0.f;
    #pragma unroll
    for (int j = 0; j < 8; j++) {
        s += v[j].x + v[j].y + v[j].z + v[j].w;
        q += v[j].x*v[j].x + v[j].y*v[j].y + v[j].z*v[j].z + v[j].w*v[j].w;
    }
    s = warp_sum32(s);
    float mean = s * (1.f / 1024.f);
    float s2 = 0.f;
    #pragma unroll
    for (int j = 0; j < 8; j++) {
        float d0 = v[j].x - mean, d1 = v[j].y - mean;
        float d2 = v[j].z - mean, d3 = v[j].w - mean;
        s2 += d0*d0 + d1*d1 + d2*d2 + d3*d3;
    }
    s2 = warp_sum32(s2);
    float rstd = rsqrtf(s2 * (1.f / 1024.f) + 1e-6f);
    const float* cmb = g_cm + b * 6 * Hc;
    #pragma unroll
    for (int j = 0; j < 8; j++) {
        int col = j * 128 + lane * 4;
        float4 sc = *(const float4*)(cmb + sco * Hc + col);
        float4 sh = *(const float4*)(cmb + so * Hc + col);
        float l0 = __bfloat162float(__float2bfloat16((v[j].x - mean) * rstd));
        float l1 = __bfloat162float(__float2bfloat16((v[j].y - mean) * rstd));
        float l2 = __bfloat162float(__float2bfloat16((v[j].z - mean) * rstd));
        float l3 = __bfloat162float(__float2bfloat16((v[j].w - mean) * rstd));
        uint2 pk;
        pk.x = pack_bf162(l0 * sc.x + sh.x, l1 * sc.y + sh.y);
        pk.y = pack_bf162(l2 * sc.z + sh.z, l3 * sc.w + sh.w);
        *(uint2*)&g_xmod[(size_t)row * Hc + col] = pk;
    }
    q = warp_sum32(q);
    if (lane == 0) sm8[w] = q;
    __syncthreads();
    if (threadIdx.x == 0) {
        float t = 0.f;
        #pragma unroll
        for (int i = 0; i < 8; i++) t += sm8[i];
        atomicAdd(&g_acc[acc_idx], t);
    }
}

// ---------------- pipelined mma.sync GEMM core (validated R7-R13) ----------------
// BM=128, BN=128, BK=64, 3 cp.async stages, 256 threads (8 warps: 4m x 2n).
#define STG 32768
#define SMEM_G 100352
#define NPERS 304   // 152 SMs x 2 CTAs: persistent grid

__device__ __forceinline__ void issue_stage(const bf16* __restrict__ A,
                                            const bf16* __restrict__ Bm, int K,
                                            int tileM, int tileN, uint32_t sbase, int kt) {
    const int tid = threadIdx.x;
    #pragma unroll
    for (int t = 0; t < 4; t++) {
        int ch = tid + t * 256;
        int row = ch >> 3, c = ch & 7;
        cp_async16(sw_addr(sbase, row, c), A + (size_t)(tileM + row) * K + kt + c * 8);
    }
    #pragma unroll
    for (int t = 0; t < 4; t++) {
        int ch = tid + t * 256;
        int row = ch >> 3, c = ch & 7;
        cp_async16(sw_addr(sbase + 16384, row, c), Bm + (size_t)(tileN + row) * K + kt + c * 8);
    }
}

__device__ __forceinline__ void gemm_core(const bf16* __restrict__ A,
                                          const bf16* __restrict__ Bm, int K,
                                          int tileM, int tileN, char* dsm,
                                          float acc[2][8][4]) {
    uint32_t sb = smem_u32(dsm);
    const int tid = threadIdx.x, lane = tid & 31, warp = tid >> 5;
    const int wm = warp & 3, wn = warp >> 2;
    const int g = lane >> 3, lr = lane & 7;
    #pragma unroll
    for (int mf = 0; mf < 2; mf++)
        #pragma unroll
        for (int nf = 0; nf < 8; nf++)
            #pragma unroll
            for (int i = 0; i < 4; i++) acc[mf][nf][i] = 0.f;

    const int nk = K >> 6;
    issue_stage(A, Bm, K, tileM, tileN, sb, 0);          CP_COMMIT;
    issue_stage(A, Bm, K, tileM, tileN, sb + STG, 64);   CP_COMMIT;

    for (int kc = 0; kc < nk; kc++) {
        CP_WAIT1;
        __syncthreads();
        uint32_t as = sb + (kc % 3) * STG;
        uint32_t bs = as + 16384;
        #pragma unroll
        for (int kk = 0; kk < 4; kk++) {
            uint32_t a0[4], a1[4], bb[4][4];
            ldsm4(a0, sw_addr(as, wm * 32 + (g & 1) * 8 + lr,      kk * 2 + (g >> 1)));
            ldsm4(a1, sw_addr(as, wm * 32 + 16 + (g & 1) * 8 + lr, kk * 2 + (g >> 1)));
            #pragma unroll
            for (int p = 0; p < 4; p++)
                ldsm4(bb[p], sw_addr(bs, wn * 64 + p * 16 + (g & 1) * 8 + lr, kk * 2 + (g >> 1)));
            #pragma unroll
            for (int p = 0; p < 4; p++) {
                mma16816(acc[0][2*p],   a0, bb[p][0], bb[p][2]);
                mma16816(acc[0][2*p+1], a0, bb[p][1], bb[p][3]);
                mma16816(acc[1][2*p],   a1, bb[p][0], bb[p][2]);
                mma16816(acc[1][2*p+1], a1, bb[p][1], bb[p][3]);
            }
        }
        if (kc + 2 < nk)
            issue_stage(A, Bm, K, tileM, tileN, sb + ((kc + 2) % 3) * STG, (kc + 2) * 64);
        CP_COMMIT;
    }
    __syncthreads();
}

#define GEMM_WCOORDS                                                \
    const int lane = threadIdx.x & 31, warp = threadIdx.x >> 5;     \
    const int wm = warp & 3, wn = warp >> 2;                        \
    const int qd = lane >> 2, c2 = (lane & 3) << 1;

// qkv (persistent, 24 N-tiles x 64 M-tiles): q scaled by (1/8)*log2(e) for exp2 softmax
#define QSCALE (0.125f * 1.4426950408889634f)
__global__ void __launch_bounds__(256, 2) k_qkv() {
    extern __shared__ char dsm[];
    GEMM_WCOORDS
    for (int t5 = blockIdx.x; t5 < 24 * 64; t5 += gridDim.x) {
        int tileM = (t5 / 24) * 128, tileN = (t5 % 24) * 128;
        float acc[2][8][4];
        gemm_core(g_xmod, g_wqT, Hc, tileM, tileN, dsm, acc);
        #pragma unroll
        for (int mf = 0; mf < 2; mf++)
            #pragma unroll
            for (int nf = 0; nf < 8; nf++)
                #pragma unroll
                for (int half = 0; half < 2; half++) {
                    int r  = tileM + wm * 32 + mf * 16 + qd + half * 8;
                    int cc = tileN + wn * 64 + nf * 8 + c2;
                    int t = cc >> 10, rem = cc & 1023;
                    int hh = rem >> 6, d = rem & 63;
                    int b = r >> 10, s = r & 1023;
                    float sc = (t == 1) ? QSCALE : 1.f;
                    uint32_t pk = pack_bf162(acc[mf][nf][half*2] * sc,
                                             acc[mf][nf][half*2+1] * sc);
                    bf16* dst = ((t == 0) ? g_k : (t == 1) ? g_q : g_v)
                                + (((size_t)(b * NHc + hh)) * Sc + s) * DHc + d;
                    *(uint32_t*)dst = pk;
                }
    }
}

// attn-out (persistent, 8 N-tiles x 64 M-tiles = 512 tiles)
__global__ void __launch_bounds__(256, 2) k_attnout(const float* __restrict__ x_in) {
    extern __shared__ char dsm[];
    float* sm8 = (float*)(dsm + 98304);
    GEMM_WCOORDS
    float ss = 0.f;
    for (int t5 = blockIdx.x; t5 < 8 * 64; t5 += gridDim.x) {
        int tileM = (t5 / 8) * 128, tileN = (t5 % 8) * 128;
        float acc[2][8][4];
        gemm_core(g_y, g_woT, Hc, tileM, tileN, dsm, acc);
        #pragma unroll
        for (int mf = 0; mf < 2; mf++)
            #pragma unroll
            for (int nf = 0; nf < 8; nf++)
                #pragma unroll
                for (int half = 0; half < 2; half++) {
                    int r  = tileM + wm * 32 + mf * 16 + qd + half * 8;
                    int cc = tileN + wn * 64 + nf * 8 + c2;
                    int b = r >> 10;
                    size_t idx = (size_t)r * Hc + cc;
                    float2 g2 = *(const float2*)&g_cm[b * 6 * Hc + 2 * Hc + cc];
                    float2 xv = *(const float2*)&x_in[idx];
                    float a0 = g2.x * acc[mf][nf][half*2];
                    float a1 = g2.y * acc[mf][nf][half*2+1];
                    *(float2*)&g_xres[idx] = make_float2(xv.x + a0, xv.y + a1);
                    ss += a0 * a0 + a1 * a1;
                }
    }
    float t = block_sum256(ss, sm8);
    if (threadIdx.x == 0) atomicAdd(&g_acc[2], t);
}

// mlp1 (persistent, 32 N-tiles x 64 M-tiles)
__global__ void __launch_bounds__(256, 2) k_mlp1() {
    extern __shared__ char dsm[];
    float* sm8 = (float*)(dsm + 98304);
    int* scnt = (int*)(dsm + 98368);
    GEMM_WCOORDS
    float ss = 0.f;
    for (int t5 = blockIdx.x; t5 < 32 * 64; t5 += gridDim.x) {
        int tileM = (t5 / 32) * 128, tileN = (t5 % 32) * 128;
        float acc[2][8][4];
        gemm_core(g_xmod, g_w1T, Hc, tileM, tileN, dsm, acc);
        if (threadIdx.x < 128) scnt[threadIdx.x] = 0;
        __syncthreads();
        #pragma unroll
        for (int nf = 0; nf < 8; nf++) {
            int cnt0 = 0, cnt1 = 0;
            #pragma unroll
            for (int mf = 0; mf < 2; mf++)
                #pragma unroll
                for (int half = 0; half < 2; half++) {
                    float t0 = acc[mf][nf][half*2], t1 = acc[mf][nf][half*2+1];
                    ss += t0 * t0 + t1 * t1;
                    cnt0 += (t0 > 0.f); cnt1 += (t1 > 0.f);
                    float u0 = 0.7978845608028654f * (t0 + 0.044715f * t0 * t0 * t0);
                    float u1 = 0.7978845608028654f * (t1 + 0.044715f * t1 * t1 * t1);
                    float g0 = 0.5f * t0 * (1.f + tanhf(u0));
                    float g1 = 0.5f * t1 * (1.f + tanhf(u1));
                    int r  = tileM + wm * 32 + mf * 16 + qd + half * 8;
                    int cc = tileN + wn * 64 + nf * 8 + c2;
                    *(uint32_t*)&g_h[(size_t)r * MLPc + cc] = pack_bf162(g0, g1);
                }
            atomicAdd(&scnt[wn * 64 + nf * 8 + c2], cnt0);
            atomicAdd(&scnt[wn * 64 + nf * 8 + c2 + 1], cnt1);
        }
        __syncthreads();
        if (threadIdx.x < 128) atomicAdd(&g_pos[tileN + threadIdx.x], scnt[threadIdx.x]);
        __syncthreads();
    }
    float t = block_sum256(ss, sm8);
    if (threadIdx.x == 0) atomicAdd(&g_acc[4], t);
}

// mlp2 (persistent, 8 N-tiles x 64 M-tiles = 512 tiles)
__global__ void __launch_bounds__(256, 2) k_mlp2(float* __restrict__ out) {
    extern __shared__ char dsm[];
    float* sm8 = (float*)(dsm + 98304);
    GEMM_WCOORDS
    float ss = 0.f;
    for (int t5 = blockIdx.x; t5 < 8 * 64; t5 += gridDim.x) {
        int tileM = (t5 / 8) * 128, tileN = (t5 % 8) * 128;
        float acc[2][8][4];
        gemm_core(g_h, g_w2T, MLPc, tileM, tileN, dsm, acc);
        #pragma unroll
        for (int mf = 0; mf < 2; mf++)
            #pragma unroll
            for (int nf = 0; nf < 8; nf++)
                #pragma unroll
                for (int half = 0; half < 2; half++) {
                    int r  = tileM + wm * 32 + mf * 16 + qd + half * 8;
                    int cc = tileN + wn * 64 + nf * 8 + c2;
                    int b = r >> 10;
                    size_t idx = (size_t)r * Hc + cc;
                    float2 g2 = *(const float2*)&g_cm[b * 6 * Hc + 5 * Hc + cc];
                    float2 xr = *(const float2*)&g_xres[idx];
                    float m0 = g2.x * acc[mf][nf][half*2];
                    float m1 = g2.y * acc[mf][nf][half*2+1];
                    *(float2*)&out[idx] = make_float2(xr.x + m0, xr.y + m1);
                    ss += m0 * m0 + m1 * m1;
                }
    }
    float t = block_sum256(ss, sm8);
    if (threadIdx.x == 0) atomicAdd(&g_acc[5], t);
}

// ---------------- flash attention (exp2 softmax; scores pre-scaled by log2e) ----------
#define ATT_SMEM 49216
__global__ void __launch_bounds__(256, 2) k_attn() {
    extern __shared__ char dsm[];
    uint32_t sb = smem_u32(dsm);
    uint32_t Qs = sb, Ks = sb + 16384, Vs = sb + 32768;
    float* sm8 = (float*)(dsm + 49152);
    const int tid = threadIdx.x, lane = tid & 31, w = tid >> 5;
    const int g = lane >> 3, lr = lane & 7;
    const int bh = blockIdx.y, qt = blockIdx.x;

    const bf16* Qg = g_q + ((size_t)bh * Sc + qt * 128) * DHc;
    const bf16* Kg = g_k + (size_t)bh * Sc * DHc;
    const bf16* Vg = g_v + (size_t)bh * Sc * DHc;

    #pragma unroll
    for (int t = 0; t < 4; t++) {
        int ch = tid + t * 256;
        int row = ch >> 3, c = ch & 7;
        cp_async16(sw_addr(Qs, row, c), Qg + (size_t)row * DHc + c * 8);
    }
    #pragma unroll
    for (int t = 0; t < 2; t++) {
        int ch = tid + t * 256;
        int row = ch >> 3, c = ch & 7;
        cp_async16(sw_addr(Ks, row, c), Kg + (size_t)row * DHc + c * 8);
        cp_async16(sw_addr(Vs, row, c), Vg + (size_t)row * DHc + c * 8);
    }
    CP_COMMIT;

    uint32_t qa[4][4];
    float O[8][4];
    #pragma unroll
    for (int nf = 0; nf < 8; nf++)
        #pragma unroll
        for (int i = 0; i < 4; i++) O[nf][i] = 0.f;
    float m0 = -1e30f, m1 = -1e30f, l0 = 0.f, l1 = 0.f;

    for (int kt = 0; kt < Sc / 64; kt++) {
        if (kt + 1 < Sc / 64) {
            int buf = (kt + 1) & 1;
            const bf16* Kn = Kg + (size_t)(kt + 1) * 64 * DHc;
            const bf16* Vn = Vg + (size_t)(kt + 1) * 64 * DHc;
            #pragma unroll
            for (int t = 0; t < 2; t++) {
                int ch = tid + t * 256;
                int row = ch >> 3, c = ch & 7;
                cp_async16(sw_addr(Ks + buf * 8192, row, c), Kn + (size_t)row * DHc + c * 8);
                cp_async16(sw_addr(Vs + buf * 8192, row, c), Vn + (size_t)row * DHc + c * 8);
            }
            CP_COMMIT;
            CP_WAIT1;
        } else {
            CP_WAIT0;
        }
        __syncthreads();
        if (kt == 0) {
            #pragma unroll
            for (int kk = 0; kk < 4; kk++)
                ldsm4(qa[kk], sw_addr(Qs, w * 16 + (g & 1) * 8 + lr, kk * 2 + (g >> 1)));
        }
        uint32_t kb = Ks + (kt & 1) * 8192;
        uint32_t vb = Vs + (kt & 1) * 8192;

        float L[8][4];
        #pragma unroll
        for (int nf = 0; nf < 8; nf++)
            #pragma unroll
            for (int i = 0; i < 4; i++) L[nf][i] = 0.f;
        #pragma unroll
        for (int kk = 0; kk < 4; kk++) {
            #pragma unroll
            for (int p = 0; p < 4; p++) {
                uint32_t b[4];
                ldsm4(b, sw_addr(kb, p * 16 + (g & 1) * 8 + lr, kk * 2 + (g >> 1)));
                mma16816(L[2*p],   qa[kk], b[0], b[2]);
                mma16816(L[2*p+1], qa[kk], b[1], b[3]);
            }
        }
        float tm0 = -1e30f, tm1 = -1e30f;
        #pragma unroll
        for (int nf = 0; nf < 8; nf++) {
            tm0 = fmaxf(tm0, fmaxf(L[nf][0], L[nf][1]));
            tm1 = fmaxf(tm1, fmaxf(L[nf][2], L[nf][3]));
        }
        tm0 = fmaxf(tm0, __shfl_xor_sync(0xffffffffu, tm0, 1));
        tm0 = fmaxf(tm0, __shfl_xor_sync(0xffffffffu, tm0, 2));
        tm1 = fmaxf(tm1, __shfl_xor_sync(0xffffffffu, tm1, 1));
        tm1 = fmaxf(tm1, __shfl_xor_sync(0xffffffffu, tm1, 2));
        float mn0 = fmaxf(m0, tm0), mn1 = fmaxf(m1, tm1);
        float cor0 = exp2f(m0 - mn0), cor1 = exp2f(m1 - mn1);
        float s0 = 0.f, s1 = 0.f;
        #pragma unroll
        for (int nf = 0; nf < 8; nf++) {
            L[nf][0] = exp2f(L[nf][0] - mn0);
            L[nf][1] = exp2f(L[nf][1] - mn0);
            L[nf][2] = exp2f(L[nf][2] - mn1);
            L[nf][3] = exp2f(L[nf][3] - mn1);
            s0 += L[nf][0] + L[nf][1];
            s1 += L[nf][2] + L[nf][3];
        }
        s0 += __shfl_xor_sync(0xffffffffu, s0, 1);
        s0 += __shfl_xor_sync(0xffffffffu, s0, 2);
        s1 += __shfl_xor_sync(0xffffffffu, s1, 1);
        s1 += __shfl_xor_sync(0xffffffffu, s1, 2);
        l0 = l0 * cor0 + s0; l1 = l1 * cor1 + s1;
        m0 = mn0; m1 = mn1;
        #pragma unroll
        for (int nf = 0; nf < 8; nf++) {
            O[nf][0] *= cor0; O[nf][1] *= cor0;
            O[nf][2] *= cor1; O[nf][3] *= cor1;
        }
        uint32_t pa[4][4];
        #pragma unroll
        for (int kk = 0; kk < 4; kk++) {
            pa[kk][0] = pack_bf162(L[2*kk][0],   L[2*kk][1]);
            pa[kk][1] = pack_bf162(L[2*kk][2],   L[2*kk][3]);
            pa[kk][2] = pack_bf162(L[2*kk+1][0], L[2*kk+1][1]);
            pa[kk][3] = pack_bf162(L[2*kk+1][2], L[2*kk+1][3]);
        }
        #pragma unroll
        for (int kk = 0; kk < 4; kk++) {
            #pragma unroll
            for (int p = 0; p < 4; p++) {
                uint32_t b[4];
                ldsm4t(b, sw_addr(vb, kk * 16 + (g & 1) * 8 + lr, p * 2 + (g >> 1)));
                mma16816(O[2*p],   pa[kk], b[0], b[1]);
                mma16816(O[2*p+1], pa[kk], b[2], b[3]);
            }
        }
        __syncthreads();
    }
    const int qd = lane >> 2, c2 = (lane & 3) << 1;
    float i0 = 1.f / l0, i1 = 1.f / l1;
    int b = bh >> 4, hh = bh & 15;
    int r0 = qt * 128 + w * 16 + qd;
    #pragma unroll
    for (int nf = 0; nf < 8; nf++) {
        size_t base0 = ((size_t)b * Sc + r0)     * Hc + hh * 64 + nf * 8 + c2;
        size_t base1 = ((size_t)b * Sc + r0 + 8) * Hc + hh * 64 + nf * 8 + c2;
        *(uint32_t*)&g_y[base0] = pack_bf162(O[nf][0] * i0, O[nf][1] * i0);
        *(uint32_t*)&g_y[base1] = pack_bf162(O[nf][2] * i1, O[nf][3] * i1);
    }
    float contrib = ((lane & 3) == 0) ? (i0 + i1) : 0.f;
    float t = block_sum256(contrib, sm8);
    if (tid == 0) atomicAdd(&g_acc[1], t);
}

// ---------------- finalize scalars ----------------
__global__ void k_fin(float* __restrict__ out, int out_size) {
    __shared__ float sm8[8];
    int tid = threadIdx.x;
    float dsum = 0.f; int zc = 0, pc = 0;
    for (int j = tid; j < MLPc; j += 256) {
        int c = g_pos[j];
        float fp = c * (1.f / 8192.f);
        dsum += fabsf(fp - 0.5f);
        zc += (c == 0);
        pc += (c == 8192);
    }
    float d = block_sum256(dsum, sm8);
    float z = block_sum256((float)zc, sm8);
    float p = block_sum256((float)pc, sm8);
    if (tid == 0 && out_size != MROWS * Hc) {
        float* o = out + (out_size - 7);
        o[0] = d * (1.f / 4096.f);
        o[1] = z * (1.f / 4096.f);
        o[2] = p * (1.f / 4096.f);
        o[3] = g_acc[1] * (1.f / 131072.f);
        o[4] = sqrtf(g_acc[2] / g_acc[0]);
        o[5] = sqrtf(g_acc[5] / g_acc[3]);
        o[6] = sqrtf(g_acc[4] / (8192.f * 4096.f));
    }
}

// ---------------- launch ----------------
extern "C" void kernel_launch(void* const* d_in, const int* in_sizes, int n_in,
                              void* d_out, int out_size) {
    const float* x      = (const float*)d_in[0];
    const float* c      = (const float*)d_in[1];
    const float* w_cond = (const float*)d_in[2];
    const float* w_qkv  = (const float*)d_in[3];
    const float* w_attn = (const float*)d_in[4];
    const float* w_mlp1 = (const float*)d_in[5];
    const float* w_mlp2 = (const float*)d_in[6];
    float* out = (float*)d_out;

    cudaFuncSetAttribute(k_qkv,     cudaFuncAttributeMaxDynamicSharedMemorySize, SMEM_G);
    cudaFuncSetAttribute(k_attnout, cudaFuncAttributeMaxDynamicSharedMemorySize, SMEM_G);
    cudaFuncSetAttribute(k_mlp1,    cudaFuncAttributeMaxDynamicSharedMemorySize, SMEM_G);
    cudaFuncSetAttribute(k_mlp2,    cudaFuncAttributeMaxDynamicSharedMemorySize, SMEM_G);
    cudaFuncSetAttribute(k_attn,    cudaFuncAttributeMaxDynamicSharedMemorySize, ATT_SMEM);

    k_prep<<<12480, 256>>>(w_qkv, w_attn, w_mlp1, w_mlp2);
    k_cond<<<dim3(24, 8), 256>>>(c, w_cond);
    k_ln_w<<<MROWS / 8, 256>>>(x, 0, 0, 1, 0);
    k_qkv<<<NPERS, 256, SMEM_G>>>();
    k_attn<<<dim3(8, Bc * NHc), 256, ATT_SMEM>>>();
    k_attnout<<<NPERS, 256, SMEM_G>>>(x);
    k_ln_w<<<MROWS / 8, 256>>>(x, 1, 3, 4, 3);
    k_mlp1<<<NPERS, 256, SMEM_G>>>();
    k_mlp2<<<NPERS, 256, SMEM_G>>>(out);
    k_fin<<<1, 256>>>(out, out_size);
}

// round 16
// speedup vs baseline: 1.1106x; 1.1106x over previous
#include <cuda_runtime.h>
#include <cuda_bf16.h>
#include <stdint.h>
#include <math.h>

typedef __nv_bfloat16 bf16;

#define Bc   8
#define Sc   1024
#define Hc   1024
#define NHc  16
#define DHc  64
#define MLPc 4096
#define MROWS (Bc*Sc)   // 8192

// ---------------- device scratch ----------------
// Weights stored bf16 in ORIGINAL [K,N] layout (no transpose; B loaded via ldsm4t)
__device__ bf16  g_wqc[Hc*3*Hc];          // [1024,3072]
__device__ bf16  g_woc[Hc*Hc];            // [1024,1024]
__device__ bf16  g_w1c[(size_t)Hc*MLPc];  // [1024,4096]
__device__ bf16  g_w2c[(size_t)MLPc*Hc];  // [4096,1024]
__device__ float g_cm[Bc*6*Hc];
__device__ bf16  g_xmod[MROWS*Hc];
__device__ bf16  g_q[Bc*NHc*Sc*DHc];
__device__ bf16  g_k[Bc*NHc*Sc*DHc];
__device__ bf16  g_v[Bc*NHc*Sc*DHc];
__device__ bf16  g_y[MROWS*Hc];
__device__ float g_xres[MROWS*Hc];
__device__ bf16  g_h[(size_t)MROWS*MLPc];
__device__ float g_acc[8];
__device__ int   g_pos[MLPc];

// ---------------- low-level helpers ----------------
__device__ __forceinline__ uint32_t smem_u32(const void* p) {
    uint32_t a;
    asm("{ .reg .u64 t; cvta.to.shared.u64 t, %1; cvt.u32.u64 %0, t; }" : "=r"(a) : "l"(p));
    return a;
}
__device__ __forceinline__ void cp_async16(uint32_t s, const void* g) {
    asm volatile("cp.async.cg.shared.global [%0], [%1], 16;" :: "r"(s), "l"(g));
}
#define CP_COMMIT asm volatile("cp.async.commit_group;" ::: "memory")
#define CP_WAIT1  asm volatile("cp.async.wait_group 1;" ::: "memory")
#define CP_WAIT0  asm volatile("cp.async.wait_group 0;" ::: "memory")

// 128B-row swizzle (A tiles, attention tiles)
__device__ __forceinline__ uint32_t sw_addr(uint32_t base, int row, int chunk) {
    return base + row * 128 + (((chunk) ^ (row & 7)) << 4);
}
// 256B-row swizzle (B tiles, [K,N] layout: 64 k-rows x 128 n-cols bf16)
__device__ __forceinline__ uint32_t sw_addrB(uint32_t base, int row, int chunk) {
    return base + row * 256 + (((chunk) ^ (row & 7)) << 4);
}
__device__ __forceinline__ void ldsm4(uint32_t r[4], uint32_t a) {
    asm volatile("ldmatrix.sync.aligned.m8n8.x4.shared.b16 {%0,%1,%2,%3}, [%4];"
                 : "=r"(r[0]), "=r"(r[1]), "=r"(r[2]), "=r"(r[3]) : "r"(a));
}
__device__ __forceinline__ void ldsm4t(uint32_t r[4], uint32_t a) {
    asm volatile("ldmatrix.sync.aligned.m8n8.x4.trans.shared.b16 {%0,%1,%2,%3}, [%4];"
                 : "=r"(r[0]), "=r"(r[1]), "=r"(r[2]), "=r"(r[3]) : "r"(a));
}
__device__ __forceinline__ void mma16816(float c[4], const uint32_t a[4],
                                         uint32_t b0, uint32_t b1) {
    asm volatile(
        "mma.sync.aligned.m16n8k16.row.col.f32.bf16.bf16.f32 "
        "{%0,%1,%2,%3},{%4,%5,%6,%7},{%8,%9},{%0,%1,%2,%3};\n"
        : "+f"(c[0]), "+f"(c[1]), "+f"(c[2]), "+f"(c[3])
        : "r"(a[0]), "r"(a[1]), "r"(a[2]), "r"(a[3]), "r"(b0), "r"(b1));
}
__device__ __forceinline__ uint32_t pack_bf162(float x, float y) {
    __nv_bfloat162 h = __floats2bfloat162_rn(x, y);
    return *(uint32_t*)&h;
}
__device__ __forceinline__ float warp_sum32(float v) {
    #pragma unroll
    for (int o = 16; o > 0; o >>= 1) v += __shfl_xor_sync(0xffffffffu, v, o);
    return v;
}
__device__ __forceinline__ float block_sum256(float v, float* sm8) {
    #pragma unroll
    for (int o = 16; o > 0; o >>= 1) v += __shfl_xor_sync(0xffffffffu, v, o);
    __syncthreads();
    if ((threadIdx.x & 31) == 0) sm8[threadIdx.x >> 5] = v;
    __syncthreads();
    float r = 0.f;
    #pragma unroll
    for (int i = 0; i < 8; i++) r += sm8[i];
    return r;
}

// ---------------- fused prep: straight f32->bf16 weight convert + zeroing ----------------
// blocks [0,12288): 1024 elems each across the 4 weight arrays; [12288,12480): zero
__global__ void k_prep(const float* __restrict__ wq, const float* __restrict__ wo,
                       const float* __restrict__ w1, const float* __restrict__ w2) {
    int id = blockIdx.x;
    if (id >= 12288) {
        int i = (id - 12288) * 256 + threadIdx.x;
        if (i < Bc * 6 * Hc) g_cm[i] = 0.f;
        if (i < MLPc) g_pos[i] = 0;
        if (i < 8)    g_acc[i] = 0.f;
        return;
    }
    const float* src; bf16* dst; long base;
    if (id < 3072)      { src = wq; dst = g_wqc; base = (long)id * 1024; }
    else if (id < 4096) { src = wo; dst = g_woc; base = (long)(id - 3072) * 1024; }
    else if (id < 8192) { src = w1; dst = g_w1c; base = (long)(id - 4096) * 1024; }
    else                { src = w2; dst = g_w2c; base = (long)(id - 8192) * 1024; }
    long i = base + threadIdx.x * 4;
    float4 v = *(const float4*)(src + i);
    uint2 pk;
    pk.x = pack_bf162(v.x, v.y);
    pk.y = pack_bf162(v.z, v.w);
    *(uint2*)(dst + i) = pk;
}

// conditioning GEMM (round-1 proven serial-K + R13 split-K hybrid kept as R13)
__global__ void k_cond(const float* __restrict__ c, const float* __restrict__ w) {
    __shared__ float ssil[Bc * 128];
    int tid = threadIdx.x;
    int kb = blockIdx.y * 128;
    for (int i = tid; i < Bc * 128; i += 256) {
        int b = i >> 7, k = i & 127;
        float v = c[b * Hc + kb + k];
        ssil[i] = v / (1.f + expf(-v));
    }
    __syncthreads();
    int j = blockIdx.x * 256 + tid;
    float acc[Bc];
    #pragma unroll
    for (int b = 0; b < Bc; b++) acc[b] = 0.f;
    for (int k = 0; k < 128; k++) {
        float wv = w[(size_t)(kb + k) * (6 * Hc) + j];
        #pragma unroll
        for (int b = 0; b < Bc; b++) acc[b] += ssil[b * 128 + k] * wv;
    }
    #pragma unroll
    for (int b = 0; b < Bc; b++) atomicAdd(&g_cm[b * 6 * Hc + j], acc[b]);
}

// Warp-per-row LayerNorm + adaLN modulate -> bf16 (validated R10)
__global__ void __launch_bounds__(256) k_ln_w(const float* __restrict__ xp,
                                              int use_xres, int so, int sco, int acc_idx) {
    __shared__ float sm8[8];
    const float* xin = use_xres ? g_xres : xp;
    const int w = threadIdx.x >> 5, lane = threadIdx.x & 31;
    const int row = blockIdx.x * 8 + w;
    const int b = row >> 10;
    const float* xr = xin + (size_t)row * Hc;
    float4 v[8];
    #pragma unroll
    for (int j = 0; j < 8; j++) v[j] = *(const float4*)(xr + j * 128 + lane * 4);
    float s = 0.f, q = 0.f;
    #pragma unroll
    for (int j = 0; j < 8; j++) {
        s += v[j].x + v[j].y + v[j].z + v[j].w;
        q += v[j].x*v[j].x + v[j].y*v[j].y + v[j].z*v[j].z + v[j].w*v[j].w;
    }
    s = warp_sum32(s);
    float mean = s * (1.f / 1024.f);
    float s2 = 0.f;
    #pragma unroll
    for (int j = 0; j < 8; j++) {
        float d0 = v[j].x - mean, d1 = v[j].y - mean;
        float d2 = v[j].z - mean, d3 = v[j].w - mean;
        s2 += d0*d0 + d1*d1 + d2*d2 + d3*d3;
    }
    s2 = warp_sum32(s2);
    float rstd = rsqrtf(s2 * (1.f / 1024.f) + 1e-6f);
    const float* cmb = g_cm + b * 6 * Hc;
    #pragma unroll
    for (int j = 0; j < 8; j++) {
        int col = j * 128 + lane * 4;
        float4 sc = *(const float4*)(cmb + sco * Hc + col);
        float4 sh = *(const float4*)(cmb + so * Hc + col);
        float l0 = __bfloat162float(__float2bfloat16((v[j].x - mean) * rstd));
        float l1 = __bfloat162float(__float2bfloat16((v[j].y - mean) * rstd));
        float l2 = __bfloat162float(__float2bfloat16((v[j].z - mean) * rstd));
        float l3 = __bfloat162float(__float2bfloat16((v[j].w - mean) * rstd));
        uint2 pk;
        pk.x = pack_bf162(l0 * sc.x + sh.x, l1 * sc.y + sh.y);
        pk.y = pack_bf162(l2 * sc.z + sh.z, l3 * sc.w + sh.w);
        *(uint2*)&g_xmod[(size_t)row * Hc + col] = pk;
    }
    q = warp_sum32(q);
    if (lane == 0) sm8[w] = q;
    __syncthreads();
    if (threadIdx.x == 0) {
        float t = 0.f;
        #pragma unroll
        for (int i = 0; i < 8; i++) t += sm8[i];
        atomicAdd(&g_acc[acc_idx], t);
    }
}

// ---------------- pipelined mma.sync GEMM core ----------------
// BM=128, BN=128, BK=64, 3 cp.async stages, 256 threads (8 warps: 4m x 2n).
// A from [M,K] (128B rows), B from [K,N] via ldsm4t (256B rows) — V-path pattern.
#define STG 32768
#define SMEM_G 100352

__device__ __forceinline__ void issue_stage(const bf16* __restrict__ A,
                                            const bf16* __restrict__ Bm, int K, int Nn,
                                            int tileM, int tileN, uint32_t sbase, int kt) {
    const int tid = threadIdx.x;
    #pragma unroll
    for (int t = 0; t < 4; t++) {
        int ch = tid + t * 256;
        int row = ch >> 3, c = ch & 7;
        cp_async16(sw_addr(sbase, row, c), A + (size_t)(tileM + row) * K + kt + c * 8);
    }
    // B tile: 64 k-rows x 128 n-cols (256B rows, 16 chunks)
    #pragma unroll
    for (int t = 0; t < 4; t++) {
        int ch = tid + t * 256;
        int row = ch >> 4, c = ch & 15;
        cp_async16(sw_addrB(sbase + 16384, row, c),
                   Bm + (size_t)(kt + row) * Nn + tileN + c * 8);
    }
}

__device__ __forceinline__ void gemm_core(const bf16* __restrict__ A,
                                          const bf16* __restrict__ Bm, int K, int Nn,
                                          int tileM, int tileN, char* dsm,
                                          float acc[2][8][4]) {
    uint32_t sb = smem_u32(dsm);
    const int tid = threadIdx.x, lane = tid & 31, warp = tid >> 5;
    const int wm = warp & 3, wn = warp >> 2;
    const int g = lane >> 3, lr = lane & 7;
    #pragma unroll
    for (int mf = 0; mf < 2; mf++)
        #pragma unroll
        for (int nf = 0; nf < 8; nf++)
            #pragma unroll
            for (int i = 0; i < 4; i++) acc[mf][nf][i] = 0.f;

    const int nk = K >> 6;
    issue_stage(A, Bm, K, Nn, tileM, tileN, sb, 0);          CP_COMMIT;
    issue_stage(A, Bm, K, Nn, tileM, tileN, sb + STG, 64);   CP_COMMIT;

    for (int kc = 0; kc < nk; kc++) {
        CP_WAIT1;
        __syncthreads();
        uint32_t as = sb + (kc % 3) * STG;
        uint32_t bs = as + 16384;
        #pragma unroll
        for (int kk = 0; kk < 4; kk++) {
            uint32_t a0[4], a1[4], bb[4][4];
            ldsm4(a0, sw_addr(as, wm * 32 + (g & 1) * 8 + lr,      kk * 2 + (g >> 1)));
            ldsm4(a1, sw_addr(as, wm * 32 + 16 + (g & 1) * 8 + lr, kk * 2 + (g >> 1)));
            #pragma unroll
            for (int p = 0; p < 4; p++)
                ldsm4t(bb[p], sw_addrB(bs, kk * 16 + (g & 1) * 8 + lr,
                                       wn * 8 + p * 2 + (g >> 1)));
            #pragma unroll
            for (int p = 0; p < 4; p++) {
                mma16816(acc[0][2*p],   a0, bb[p][0], bb[p][1]);
                mma16816(acc[0][2*p+1], a0, bb[p][2], bb[p][3]);
                mma16816(acc[1][2*p],   a1, bb[p][0], bb[p][1]);
                mma16816(acc[1][2*p+1], a1, bb[p][2], bb[p][3]);
            }
        }
        if (kc + 2 < nk)
            issue_stage(A, Bm, K, Nn, tileM, tileN, sb + ((kc + 2) % 3) * STG, (kc + 2) * 64);
        CP_COMMIT;
    }
    __syncthreads();
}

#define GEMM_EPI_COORDS                                             \
    const int lane = threadIdx.x & 31, warp = threadIdx.x >> 5;     \
    const int wm = warp & 3, wn = warp >> 2;                        \
    const int qd = lane >> 2, c2 = (lane & 3) << 1;                 \
    const int tileM = blockIdx.y * 128, tileN = blockIdx.x * 128;

// qkv: split cols (k,q,v); q scaled by (1/8)*log2(e) for exp2 softmax
#define QSCALE (0.125f * 1.4426950408889634f)
__global__ void __launch_bounds__(256, 2) k_qkv() {
    extern __shared__ char dsm[];
    float acc[2][8][4];
    gemm_core(g_xmod, g_wqc, Hc, 3*Hc, blockIdx.y * 128, blockIdx.x * 128, dsm, acc);
    GEMM_EPI_COORDS
    #pragma unroll
    for (int mf = 0; mf < 2; mf++)
        #pragma unroll
        for (int nf = 0; nf < 8; nf++)
            #pragma unroll
            for (int half = 0; half < 2; half++) {
                int r  = tileM + wm * 32 + mf * 16 + qd + half * 8;
                int cc = tileN + wn * 64 + nf * 8 + c2;
                int t = cc >> 10, rem = cc & 1023;
                int hh = rem >> 6, d = rem & 63;
                int b = r >> 10, s = r & 1023;
                float sc = (t == 1) ? QSCALE : 1.f;
                uint32_t pk = pack_bf162(acc[mf][nf][half*2] * sc,
                                         acc[mf][nf][half*2+1] * sc);
                bf16* dst = ((t == 0) ? g_k : (t == 1) ? g_q : g_v)
                            + (((size_t)(b * NHc + hh)) * Sc + s) * DHc + d;
                *(uint32_t*)dst = pk;
            }
}

// attn-out: x_res = x + gate_msa*acc ; sumsq_attn
__global__ void __launch_bounds__(256, 2) k_attnout(const float* __restrict__ x_in) {
    extern __shared__ char dsm[];
    float* sm8 = (float*)(dsm + 98304);
    float acc[2][8][4];
    gemm_core(g_y, g_woc, Hc, Hc, blockIdx.y * 128, blockIdx.x * 128, dsm, acc);
    GEMM_EPI_COORDS
    float ss = 0.f;
    #pragma unroll
    for (int mf = 0; mf < 2; mf++)
        #pragma unroll
        for (int nf = 0; nf < 8; nf++)
            #pragma unroll
            for (int half = 0; half < 2; half++) {
                int r  = tileM + wm * 32 + mf * 16 + qd + half * 8;
                int cc = tileN + wn * 64 + nf * 8 + c2;
                int b = r >> 10;
                size_t idx = (size_t)r * Hc + cc;
                float2 g2 = *(const float2*)&g_cm[b * 6 * Hc + 2 * Hc + cc];
                float2 xv = *(const float2*)&x_in[idx];
                float a0 = g2.x * acc[mf][nf][half*2];
                float a1 = g2.y * acc[mf][nf][half*2+1];
                *(float2*)&g_xres[idx] = make_float2(xv.x + a0, xv.y + a1);
                ss += a0 * a0 + a1 * a1;
            }
    float t = block_sum256(ss, sm8);
    if (threadIdx.x == 0) atomicAdd(&g_acc[2], t);
}

// mlp1: positive counts, sumsq_relu, tanh-gelu -> bf16 h
__global__ void __launch_bounds__(256, 2) k_mlp1() {
    extern __shared__ char dsm[];
    float* sm8 = (float*)(dsm + 98304);
    int* scnt = (int*)(dsm + 98368);
    if (threadIdx.x < 128) scnt[threadIdx.x] = 0;
    float acc[2][8][4];
    gemm_core(g_xmod, g_w1c, Hc, MLPc, blockIdx.y * 128, blockIdx.x * 128, dsm, acc);
    GEMM_EPI_COORDS
    float ss = 0.f;
    #pragma unroll
    for (int nf = 0; nf < 8; nf++) {
        int cnt0 = 0, cnt1 = 0;
        #pragma unroll
        for (int mf = 0; mf < 2; mf++)
            #pragma unroll
            for (int half = 0; half < 2; half++) {
                float t0 = acc[mf][nf][half*2], t1 = acc[mf][nf][half*2+1];
                ss += t0 * t0 + t1 * t1;
                cnt0 += (t0 > 0.f); cnt1 += (t1 > 0.f);
                float u0 = 0.7978845608028654f * (t0 + 0.044715f * t0 * t0 * t0);
                float u1 = 0.7978845608028654f * (t1 + 0.044715f * t1 * t1 * t1);
                float g0 = 0.5f * t0 * (1.f + tanhf(u0));
                float g1 = 0.5f * t1 * (1.f + tanhf(u1));
                int r  = tileM + wm * 32 + mf * 16 + qd + half * 8;
                int cc = tileN + wn * 64 + nf * 8 + c2;
                *(uint32_t*)&g_h[(size_t)r * MLPc + cc] = pack_bf162(g0, g1);
            }
        atomicAdd(&scnt[wn * 64 + nf * 8 + c2], cnt0);
        atomicAdd(&scnt[wn * 64 + nf * 8 + c2 + 1], cnt1);
    }
    __syncthreads();
    if (threadIdx.x < 128) atomicAdd(&g_pos[tileN + threadIdx.x], scnt[threadIdx.x]);
    float t = block_sum256(ss, sm8);
    if (threadIdx.x == 0) atomicAdd(&g_acc[4], t);
}

// mlp2: out = x_res + gate_mlp*acc ; sumsq_mlp
__global__ void __launch_bounds__(256, 2) k_mlp2(float* __restrict__ out) {
    extern __shared__ char dsm[];
    float* sm8 = (float*)(dsm + 98304);
    float acc[2][8][4];
    gemm_core(g_h, g_w2c, MLPc, Hc, blockIdx.y * 128, blockIdx.x * 128, dsm, acc);
    GEMM_EPI_COORDS
    float ss = 0.f;
    #pragma unroll
    for (int mf = 0; mf < 2; mf++)
        #pragma unroll
        for (int nf = 0; nf < 8; nf++)
            #pragma unroll
            for (int half = 0; half < 2; half++) {
                int r  = tileM + wm * 32 + mf * 16 + qd + half * 8;
                int cc = tileN + wn * 64 + nf * 8 + c2;
                int b = r >> 10;
                size_t idx = (size_t)r * Hc + cc;
                float2 g2 = *(const float2*)&g_cm[b * 6 * Hc + 5 * Hc + cc];
                float2 xr = *(const float2*)&g_xres[idx];
                float m0 = g2.x * acc[mf][nf][half*2];
                float m1 = g2.y * acc[mf][nf][half*2+1];
                *(float2*)&out[idx] = make_float2(xr.x + m0, xr.y + m1);
                ss += m0 * m0 + m1 * m1;
            }
    float t = block_sum256(ss, sm8);
    if (threadIdx.x == 0) atomicAdd(&g_acc[5], t);
}

// ---------------- flash attention (exp2 softmax; scores pre-scaled by log2e) ----------
#define ATT_SMEM 49216
__global__ void __launch_bounds__(256, 2) k_attn() {
    extern __shared__ char dsm[];
    uint32_t sb = smem_u32(dsm);
    uint32_t Qs = sb, Ks = sb + 16384, Vs = sb + 32768;
    float* sm8 = (float*)(dsm + 49152);
    const int tid = threadIdx.x, lane = tid & 31, w = tid >> 5;
    const int g = lane >> 3, lr = lane & 7;
    const int bh = blockIdx.y, qt = blockIdx.x;

    const bf16* Qg = g_q + ((size_t)bh * Sc + qt * 128) * DHc;
    const bf16* Kg = g_k + (size_t)bh * Sc * DHc;
    const bf16* Vg = g_v + (size_t)bh * Sc * DHc;

    #pragma unroll
    for (int t = 0; t < 4; t++) {
        int ch = tid + t * 256;
        int row = ch >> 3, c = ch & 7;
        cp_async16(sw_addr(Qs, row, c), Qg + (size_t)row * DHc + c * 8);
    }
    #pragma unroll
    for (int t = 0; t < 2; t++) {
        int ch = tid + t * 256;
        int row = ch >> 3, c = ch & 7;
        cp_async16(sw_addr(Ks, row, c), Kg + (size_t)row * DHc + c * 8);
        cp_async16(sw_addr(Vs, row, c), Vg + (size_t)row * DHc + c * 8);
    }
    CP_COMMIT;

    uint32_t qa[4][4];
    float O[8][4];
    #pragma unroll
    for (int nf = 0; nf < 8; nf++)
        #pragma unroll
        for (int i = 0; i < 4; i++) O[nf][i] = 0.f;
    float m0 = -1e30f, m1 = -1e30f, l0 = 0.f, l1 = 0.f;

    for (int kt = 0; kt < Sc / 64; kt++) {
        if (kt + 1 < Sc / 64) {
            int buf = (kt + 1) & 1;
            const bf16* Kn = Kg + (size_t)(kt + 1) * 64 * DHc;
            const bf16* Vn = Vg + (size_t)(kt + 1) * 64 * DHc;
            #pragma unroll
            for (int t = 0; t < 2; t++) {
                int ch = tid + t * 256;
                int row = ch >> 3, c = ch & 7;
                cp_async16(sw_addr(Ks + buf * 8192, row, c), Kn + (size_t)row * DHc + c * 8);
                cp_async16(sw_addr(Vs + buf * 8192, row, c), Vn + (size_t)row * DHc + c * 8);
            }
            CP_COMMIT;
            CP_WAIT1;
        } else {
            CP_WAIT0;
        }
        __syncthreads();
        if (kt == 0) {
            #pragma unroll
            for (int kk = 0; kk < 4; kk++)
                ldsm4(qa[kk], sw_addr(Qs, w * 16 + (g & 1) * 8 + lr, kk * 2 + (g >> 1)));
        }
        uint32_t kb = Ks + (kt & 1) * 8192;
        uint32_t vb = Vs + (kt & 1) * 8192;

        float L[8][4];
        #pragma unroll
        for (int nf = 0; nf < 8; nf++)
            #pragma unroll
            for (int i = 0; i < 4; i++) L[nf][i] = 0.f;
        #pragma unroll
        for (int kk = 0; kk < 4; kk++) {
            #pragma unroll
            for (int p = 0; p < 4; p++) {
                uint32_t b[4];
                ldsm4(b, sw_addr(kb, p * 16 + (g & 1) * 8 + lr, kk * 2 + (g >> 1)));
                mma16816(L[2*p],   qa[kk], b[0], b[2]);
                mma16816(L[2*p+1], qa[kk], b[1], b[3]);
            }
        }
        float tm0 = -1e30f, tm1 = -1e30f;
        #pragma unroll
        for (int nf = 0; nf < 8; nf++) {
            tm0 = fmaxf(tm0, fmaxf(L[nf][0], L[nf][1]));
            tm1 = fmaxf(tm1, fmaxf(L[nf][2], L[nf][3]));
        }
        tm0 = fmaxf(tm0, __shfl_xor_sync(0xffffffffu, tm0, 1));
        tm0 = fmaxf(tm0, __shfl_xor_sync(0xffffffffu, tm0, 2));
        tm1 = fmaxf(tm1, __shfl_xor_sync(0xffffffffu, tm1, 1));
        tm1 = fmaxf(tm1, __shfl_xor_sync(0xffffffffu, tm1, 2));
        float mn0 = fmaxf(m0, tm0), mn1 = fmaxf(m1, tm1);
        float cor0 = exp2f(m0 - mn0), cor1 = exp2f(m1 - mn1);
        float s0 = 0.f, s1 = 0.f;
        #pragma unroll
        for (int nf = 0; nf < 8; nf++) {
            L[nf][0] = exp2f(L[nf][0] - mn0);
            L[nf][1] = exp2f(L[nf][1] - mn0);
            L[nf][2] = exp2f(L[nf][2] - mn1);
            L[nf][3] = exp2f(L[nf][3] - mn1);
            s0 += L[nf][0] + L[nf][1];
            s1 += L[nf][2] + L[nf][3];
        }
        s0 += __shfl_xor_sync(0xffffffffu, s0, 1);
        s0 += __shfl_xor_sync(0xffffffffu, s0, 2);
        s1 += __shfl_xor_sync(0xffffffffu, s1, 1);
        s1 += __shfl_xor_sync(0xffffffffu, s1, 2);
        l0 = l0 * cor0 + s0; l1 = l1 * cor1 + s1;
        m0 = mn0; m1 = mn1;
        #pragma unroll
        for (int nf = 0; nf < 8; nf++) {
            O[nf][0] *= cor0; O[nf][1] *= cor0;
            O[nf][2] *= cor1; O[nf][3] *= cor1;
        }
        uint32_t pa[4][4];
        #pragma unroll
        for (int kk = 0; kk < 4; kk++) {
            pa[kk][0] = pack_bf162(L[2*kk][0],   L[2*kk][1]);
            pa[kk][1] = pack_bf162(L[2*kk][2],   L[2*kk][3]);
            pa[kk][2] = pack_bf162(L[2*kk+1][0], L[2*kk+1][1]);
            pa[kk][3] = pack_bf162(L[2*kk+1][2], L[2*kk+1][3]);
        }
        #pragma unroll
        for (int kk = 0; kk < 4; kk++) {
            #pragma unroll
            for (int p = 0; p < 4; p++) {
                uint32_t b[4];
                ldsm4t(b, sw_addr(vb, kk * 16 + (g & 1) * 8 + lr, p * 2 + (g >> 1)));
                mma16816(O[2*p],   pa[kk], b[0], b[1]);
                mma16816(O[2*p+1], pa[kk], b[2], b[3]);
            }
        }
        __syncthreads();
    }
    const int qd = lane >> 2, c2 = (lane & 3) << 1;
    float i0 = 1.f / l0, i1 = 1.f / l1;
    int b = bh >> 4, hh = bh & 15;
    int r0 = qt * 128 + w * 16 + qd;
    #pragma unroll
    for (int nf = 0; nf < 8; nf++) {
        size_t base0 = ((size_t)b * Sc + r0)     * Hc + hh * 64 + nf * 8 + c2;
        size_t base1 = ((size_t)b * Sc + r0 + 8) * Hc + hh * 64 + nf * 8 + c2;
        *(uint32_t*)&g_y[base0] = pack_bf162(O[nf][0] * i0, O[nf][1] * i0);
        *(uint32_t*)&g_y[base1] = pack_bf162(O[nf][2] * i1, O[nf][3] * i1);
    }
    float contrib = ((lane & 3) == 0) ? (i0 + i1) : 0.f;
    float t = block_sum256(contrib, sm8);
    if (tid == 0) atomicAdd(&g_acc[1], t);
}

// ---------------- finalize scalars ----------------
__global__ void k_fin(float* __restrict__ out, int out_size) {
    __shared__ float sm8[8];
    int tid = threadIdx.x;
    float dsum = 0.f; int zc = 0, pc = 0;
    for (int j = tid; j < MLPc; j += 256) {
        int c = g_pos[j];
        float fp = c * (1.f / 8192.f);
        dsum += fabsf(fp - 0.5f);
        zc += (c == 0);
        pc += (c == 8192);
    }
    float d = block_sum256(dsum, sm8);
    float z = block_sum256((float)zc, sm8);
    float p = block_sum256((float)pc, sm8);
    if (tid == 0 && out_size != MROWS * Hc) {
        float* o = out + (out_size - 7);
        o[0] = d * (1.f / 4096.f);
        o[1] = z * (1.f / 4096.f);
        o[2] = p * (1.f / 4096.f);
        o[3] = g_acc[1] * (1.f / 131072.f);
        o[4] = sqrtf(g_acc[2] / g_acc[0]);
        o[5] = sqrtf(g_acc[5] / g_acc[3]);
        o[6] = sqrtf(g_acc[4] / (8192.f * 4096.f));
    }
}

// ---------------- launch (R13 grids) ----------------
extern "C" void kernel_launch(void* const* d_in, const int* in_sizes, int n_in,
                              void* d_out, int out_size) {
    const float* x      = (const float*)d_in[0];
    const float* c      = (const float*)d_in[1];
    const float* w_cond = (const float*)d_in[2];
    const float* w_qkv  = (const float*)d_in[3];
    const float* w_attn = (const float*)d_in[4];
    const float* w_mlp1 = (const float*)d_in[5];
    const float* w_mlp2 = (const float*)d_in[6];
    float* out = (float*)d_out;

    cudaFuncSetAttribute(k_qkv,     cudaFuncAttributeMaxDynamicSharedMemorySize, SMEM_G);
    cudaFuncSetAttribute(k_attnout, cudaFuncAttributeMaxDynamicSharedMemorySize, SMEM_G);
    cudaFuncSetAttribute(k_mlp1,    cudaFuncAttributeMaxDynamicSharedMemorySize, SMEM_G);
    cudaFuncSetAttribute(k_mlp2,    cudaFuncAttributeMaxDynamicSharedMemorySize, SMEM_G);
    cudaFuncSetAttribute(k_attn,    cudaFuncAttributeMaxDynamicSharedMemorySize, ATT_SMEM);

    k_prep<<<12480, 256>>>(w_qkv, w_attn, w_mlp1, w_mlp2);
    k_cond<<<dim3(24, 8), 256>>>(c, w_cond);
    k_ln_w<<<MROWS / 8, 256>>>(x, 0, 0, 1, 0);
    k_qkv<<<dim3(24, 64), 256, SMEM_G>>>();
    k_attn<<<dim3(8, Bc * NHc), 256, ATT_SMEM>>>();
    k_attnout<<<dim3(8, 64), 256, SMEM_G>>>(x);
    k_ln_w<<<MROWS / 8, 256>>>(x, 1, 3, 4, 3);
    k_mlp1<<<dim3(32, 64), 256, SMEM_G>>>();
    k_mlp2<<<dim3(8, 64), 256, SMEM_G>>>(out);
    k_fin<<<1, 256>>>(out, out_size);
}

// round 17
// speedup vs baseline: 1.1128x; 1.0020x over previous
#include <cuda_runtime.h>
#include <cuda_bf16.h>
#include <stdint.h>
#include <math.h>

typedef __nv_bfloat16 bf16;

#define Bc   8
#define Sc   1024
#define Hc   1024
#define NHc  16
#define DHc  64
#define MLPc 4096
#define MROWS (Bc*Sc)   // 8192

// ---------------- device scratch ----------------
// Weights stored bf16 in ORIGINAL [K,N] layout (B loaded via ldsm4t)
__device__ bf16  g_wqc[Hc*3*Hc];          // [1024,3072]
__device__ bf16  g_woc[Hc*Hc];            // [1024,1024]
__device__ bf16  g_w1c[(size_t)Hc*MLPc];  // [1024,4096]
__device__ bf16  g_w2c[(size_t)MLPc*Hc];  // [4096,1024]
__device__ float g_cm[Bc*6*Hc];
__device__ bf16  g_xmod[MROWS*Hc];
__device__ bf16  g_q[Bc*NHc*Sc*DHc];
__device__ bf16  g_k[Bc*NHc*Sc*DHc];
__device__ bf16  g_v[Bc*NHc*Sc*DHc];
__device__ bf16  g_y[MROWS*Hc];
__device__ float g_xres[MROWS*Hc];
__device__ bf16  g_h[(size_t)MROWS*MLPc];
__device__ float g_acc[8];
__device__ int   g_pos[MLPc];

// ---------------- low-level helpers ----------------
__device__ __forceinline__ uint32_t smem_u32(const void* p) {
    uint32_t a;
    asm("{ .reg .u64 t; cvta.to.shared.u64 t, %1; cvt.u32.u64 %0, t; }" : "=r"(a) : "l"(p));
    return a;
}
__device__ __forceinline__ void cp_async16(uint32_t s, const void* g) {
    asm volatile("cp.async.cg.shared.global [%0], [%1], 16;" :: "r"(s), "l"(g));
}
#define CP_COMMIT asm volatile("cp.async.commit_group;" ::: "memory")
#define CP_WAIT1  asm volatile("cp.async.wait_group 1;" ::: "memory")

// 128B-row swizzle (A tiles, attention tiles)
__device__ __forceinline__ uint32_t sw_addr(uint32_t base, int row, int chunk) {
    return base + row * 128 + (((chunk) ^ (row & 7)) << 4);
}
// 256B-row swizzle (B tiles, [K,N] layout: 64 k-rows x 128 n-cols bf16)
__device__ __forceinline__ uint32_t sw_addrB(uint32_t base, int row, int chunk) {
    return base + row * 256 + (((chunk) ^ (row & 7)) << 4);
}
__device__ __forceinline__ void ldsm4(uint32_t r[4], uint32_t a) {
    asm volatile("ldmatrix.sync.aligned.m8n8.x4.shared.b16 {%0,%1,%2,%3}, [%4];"
                 : "=r"(r[0]), "=r"(r[1]), "=r"(r[2]), "=r"(r[3]) : "r"(a));
}
__device__ __forceinline__ void ldsm4t(uint32_t r[4], uint32_t a) {
    asm volatile("ldmatrix.sync.aligned.m8n8.x4.trans.shared.b16 {%0,%1,%2,%3}, [%4];"
                 : "=r"(r[0]), "=r"(r[1]), "=r"(r[2]), "=r"(r[3]) : "r"(a));
}
__device__ __forceinline__ void mma16816(float c[4], const uint32_t a[4],
                                         uint32_t b0, uint32_t b1) {
    asm volatile(
        "mma.sync.aligned.m16n8k16.row.col.f32.bf16.bf16.f32 "
        "{%0,%1,%2,%3},{%4,%5,%6,%7},{%8,%9},{%0,%1,%2,%3};\n"
        : "+f"(c[0]), "+f"(c[1]), "+f"(c[2]), "+f"(c[3])
        : "r"(a[0]), "r"(a[1]), "r"(a[2]), "r"(a[3]), "r"(b0), "r"(b1));
}
__device__ __forceinline__ uint32_t pack_bf162(float x, float y) {
    __nv_bfloat162 h = __floats2bfloat162_rn(x, y);
    return *(uint32_t*)&h;
}
__device__ __forceinline__ float warp_sum32(float v) {
    #pragma unroll
    for (int o = 16; o > 0; o >>= 1) v += __shfl_xor_sync(0xffffffffu, v, o);
    return v;
}
__device__ __forceinline__ float block_sum256(float v, float* sm8) {
    #pragma unroll
    for (int o = 16; o > 0; o >>= 1) v += __shfl_xor_sync(0xffffffffu, v, o);
    __syncthreads();
    if ((threadIdx.x & 31) == 0) sm8[threadIdx.x >> 5] = v;
    __syncthreads();
    float r = 0.f;
    #pragma unroll
    for (int i = 0; i < 8; i++) r += sm8[i];
    return r;
}

// ---------------- fused prep: straight f32->bf16 weight convert + zeroing ----------------
__global__ void k_prep(const float* __restrict__ wq, const float* __restrict__ wo,
                       const float* __restrict__ w1, const float* __restrict__ w2) {
    int id = blockIdx.x;
    if (id >= 12288) {
        int i = (id - 12288) * 256 + threadIdx.x;
        if (i < Bc * 6 * Hc) g_cm[i] = 0.f;
        if (i < MLPc) g_pos[i] = 0;
        if (i < 8)    g_acc[i] = 0.f;
        return;
    }
    const float* src; bf16* dst; long base;
    if (id < 3072)      { src = wq; dst = g_wqc; base = (long)id * 1024; }
    else if (id < 4096) { src = wo; dst = g_woc; base = (long)(id - 3072) * 1024; }
    else if (id < 8192) { src = w1; dst = g_w1c; base = (long)(id - 4096) * 1024; }
    else                { src = w2; dst = g_w2c; base = (long)(id - 8192) * 1024; }
    long i = base + threadIdx.x * 4;
    float4 v = *(const float4*)(src + i);
    uint2 pk;
    pk.x = pack_bf162(v.x, v.y);
    pk.y = pack_bf162(v.z, v.w);
    *(uint2*)(dst + i) = pk;
}

// split-K conditioning GEMM
__global__ void k_cond(const float* __restrict__ c, const float* __restrict__ w) {
    __shared__ float ssil[Bc * 128];
    int tid = threadIdx.x;
    int kb = blockIdx.y * 128;
    for (int i = tid; i < Bc * 128; i += 256) {
        int b = i >> 7, k = i & 127;
        float v = c[b * Hc + kb + k];
        ssil[i] = v / (1.f + expf(-v));
    }
    __syncthreads();
    int j = blockIdx.x * 256 + tid;
    float acc[Bc];
    #pragma unroll
    for (int b = 0; b < Bc; b++) acc[b] = 0.f;
    for (int k = 0; k < 128; k++) {
        float wv = w[(size_t)(kb + k) * (6 * Hc) + j];
        #pragma unroll
        for (int b = 0; b < Bc; b++) acc[b] += ssil[b * 128 + k] * wv;
    }
    #pragma unroll
    for (int b = 0; b < Bc; b++) atomicAdd(&g_cm[b * 6 * Hc + j], acc[b]);
}

// Warp-per-row LayerNorm + adaLN modulate -> bf16 (validated R10)
__global__ void __launch_bounds__(256) k_ln_w(const float* __restrict__ xp,
                                              int use_xres, int so, int sco, int acc_idx) {
    __shared__ float sm8[8];
    const float* xin = use_xres ? g_xres : xp;
    const int w = threadIdx.x >> 5, lane = threadIdx.x & 31;
    const int row = blockIdx.x * 8 + w;
    const int b = row >> 10;
    const float* xr = xin + (size_t)row * Hc;
    float4 v[8];
    #pragma unroll
    for (int j = 0; j < 8; j++) v[j] = *(const float4*)(xr + j * 128 + lane * 4);
    float s = 0.f, q = 0.f;
    #pragma unroll
    for (int j = 0; j < 8; j++) {
        s += v[j].x + v[j].y + v[j].z + v[j].w;
        q += v[j].x*v[j].x + v[j].y*v[j].y + v[j].z*v[j].z + v[j].w*v[j].w;
    }
    s = warp_sum32(s);
    float mean = s * (1.f / 1024.f);
    float s2 = 0.f;
    #pragma unroll
    for (int j = 0; j < 8; j++) {
        float d0 = v[j].x - mean, d1 = v[j].y - mean;
        float d2 = v[j].z - mean, d3 = v[j].w - mean;
        s2 += d0*d0 + d1*d1 + d2*d2 + d3*d3;
    }
    s2 = warp_sum32(s2);
    float rstd = rsqrtf(s2 * (1.f / 1024.f) + 1e-6f);
    const float* cmb = g_cm + b * 6 * Hc;
    #pragma unroll
    for (int j = 0; j < 8; j++) {
        int col = j * 128 + lane * 4;
        float4 sc = *(const float4*)(cmb + sco * Hc + col);
        float4 sh = *(const float4*)(cmb + so * Hc + col);
        float l0 = __bfloat162float(__float2bfloat16((v[j].x - mean) * rstd));
        float l1 = __bfloat162float(__float2bfloat16((v[j].y - mean) * rstd));
        float l2 = __bfloat162float(__float2bfloat16((v[j].z - mean) * rstd));
        float l3 = __bfloat162float(__float2bfloat16((v[j].w - mean) * rstd));
        uint2 pk;
        pk.x = pack_bf162(l0 * sc.x + sh.x, l1 * sc.y + sh.y);
        pk.y = pack_bf162(l2 * sc.z + sh.z, l3 * sc.w + sh.w);
        *(uint2*)&g_xmod[(size_t)row * Hc + col] = pk;
    }
    q = warp_sum32(q);
    if (lane == 0) sm8[w] = q;
    __syncthreads();
    if (threadIdx.x == 0) {
        float t = 0.f;
        #pragma unroll
        for (int i = 0; i < 8; i++) t += sm8[i];
        atomicAdd(&g_acc[acc_idx], t);
    }
}

// ---------------- pipelined mma.sync GEMM core (validated R16) ----------------
// BM=128, BN=128, BK=64, 3 cp.async stages, 256 threads (8 warps: 4m x 2n).
// A from [M,K] (128B rows), B from [K,N] via ldsm4t (256B rows).
#define STG 32768
#define SMEM_G 100352

__device__ __forceinline__ void issue_stage(const bf16* __restrict__ A,
                                            const bf16* __restrict__ Bm, int K, int Nn,
                                            int tileM, int tileN, uint32_t sbase, int kt) {
    const int tid = threadIdx.x;
    #pragma unroll
    for (int t = 0; t < 4; t++) {
        int ch = tid + t * 256;
        int row = ch >> 3, c = ch & 7;
        cp_async16(sw_addr(sbase, row, c), A + (size_t)(tileM + row) * K + kt + c * 8);
    }
    #pragma unroll
    for (int t = 0; t < 4; t++) {
        int ch = tid + t * 256;
        int row = ch >> 4, c = ch & 15;
        cp_async16(sw_addrB(sbase + 16384, row, c),
                   Bm + (size_t)(kt + row) * Nn + tileN + c * 8);
    }
}

__device__ __forceinline__ void gemm_core(const bf16* __restrict__ A,
                                          const bf16* __restrict__ Bm, int K, int Nn,
                                          int tileM, int tileN, char* dsm,
                                          float acc[2][8][4]) {
    uint32_t sb = smem_u32(dsm);
    const int tid = threadIdx.x, lane = tid & 31, warp = tid >> 5;
    const int wm = warp & 3, wn = warp >> 2;
    const int g = lane >> 3, lr = lane & 7;
    #pragma unroll
    for (int mf = 0; mf < 2; mf++)
        #pragma unroll
        for (int nf = 0; nf < 8; nf++)
            #pragma unroll
            for (int i = 0; i < 4; i++) acc[mf][nf][i] = 0.f;

    const int nk = K >> 6;
    issue_stage(A, Bm, K, Nn, tileM, tileN, sb, 0);          CP_COMMIT;
    issue_stage(A, Bm, K, Nn, tileM, tileN, sb + STG, 64);   CP_COMMIT;

    for (int kc = 0; kc < nk; kc++) {
        CP_WAIT1;
        __syncthreads();
        uint32_t as = sb + (kc % 3) * STG;
        uint32_t bs = as + 16384;
        #pragma unroll
        for (int kk = 0; kk < 4; kk++) {
            uint32_t a0[4], a1[4], bb[4][4];
            ldsm4(a0, sw_addr(as, wm * 32 + (g & 1) * 8 + lr,      kk * 2 + (g >> 1)));
            ldsm4(a1, sw_addr(as, wm * 32 + 16 + (g & 1) * 8 + lr, kk * 2 + (g >> 1)));
            #pragma unroll
            for (int p = 0; p < 4; p++)
                ldsm4t(bb[p], sw_addrB(bs, kk * 16 + (g & 1) * 8 + lr,
                                       wn * 8 + p * 2 + (g >> 1)));
            #pragma unroll
            for (int p = 0; p < 4; p++) {
                mma16816(acc[0][2*p],   a0, bb[p][0], bb[p][1]);
                mma16816(acc[0][2*p+1], a0, bb[p][2], bb[p][3]);
                mma16816(acc[1][2*p],   a1, bb[p][0], bb[p][1]);
                mma16816(acc[1][2*p+1], a1, bb[p][2], bb[p][3]);
            }
        }
        if (kc + 2 < nk)
            issue_stage(A, Bm, K, Nn, tileM, tileN, sb + ((kc + 2) % 3) * STG, (kc + 2) * 64);
        CP_COMMIT;
    }
    __syncthreads();
}

#define GEMM_EPI_COORDS                                             \
    const int lane = threadIdx.x & 31, warp = threadIdx.x >> 5;     \
    const int wm = warp & 3, wn = warp >> 2;                        \
    const int qd = lane >> 2, c2 = (lane & 3) << 1;                 \
    const int tileM = blockIdx.y * 128, tileN = blockIdx.x * 128;

// qkv: split cols (k,q,v); q scaled by (1/8)*log2(e) for exp2 softmax
#define QSCALE (0.125f * 1.4426950408889634f)
__global__ void __launch_bounds__(256, 2) k_qkv() {
    extern __shared__ char dsm[];
    float acc[2][8][4];
    gemm_core(g_xmod, g_wqc, Hc, 3*Hc, blockIdx.y * 128, blockIdx.x * 128, dsm, acc);
    GEMM_EPI_COORDS
    #pragma unroll
    for (int mf = 0; mf < 2; mf++)
        #pragma unroll
        for (int nf = 0; nf < 8; nf++)
            #pragma unroll
            for (int half = 0; half < 2; half++) {
                int r  = tileM + wm * 32 + mf * 16 + qd + half * 8;
                int cc = tileN + wn * 64 + nf * 8 + c2;
                int t = cc >> 10, rem = cc & 1023;
                int hh = rem >> 6, d = rem & 63;
                int b = r >> 10, s = r & 1023;
                float sc = (t == 1) ? QSCALE : 1.f;
                uint32_t pk = pack_bf162(acc[mf][nf][half*2] * sc,
                                         acc[mf][nf][half*2+1] * sc);
                bf16* dst = ((t == 0) ? g_k : (t == 1) ? g_q : g_v)
                            + (((size_t)(b * NHc + hh)) * Sc + s) * DHc + d;
                *(uint32_t*)dst = pk;
            }
}

// attn-out: x_res = x + gate_msa*acc ; sumsq_attn
__global__ void __launch_bounds__(256, 2) k_attnout(const float* __restrict__ x_in) {
    extern __shared__ char dsm[];
    float* sm8 = (float*)(dsm + 98304);
    float acc[2][8][4];
    gemm_core(g_y, g_woc, Hc, Hc, blockIdx.y * 128, blockIdx.x * 128, dsm, acc);
    GEMM_EPI_COORDS
    float ss = 0.f;
    #pragma unroll
    for (int mf = 0; mf < 2; mf++)
        #pragma unroll
        for (int nf = 0; nf < 8; nf++)
            #pragma unroll
            for (int half = 0; half < 2; half++) {
                int r  = tileM + wm * 32 + mf * 16 + qd + half * 8;
                int cc = tileN + wn * 64 + nf * 8 + c2;
                int b = r >> 10;
                size_t idx = (size_t)r * Hc + cc;
                float2 g2 = *(const float2*)&g_cm[b * 6 * Hc + 2 * Hc + cc];
                float2 xv = *(const float2*)&x_in[idx];
                float a0 = g2.x * acc[mf][nf][half*2];
                float a1 = g2.y * acc[mf][nf][half*2+1];
                *(float2*)&g_xres[idx] = make_float2(xv.x + a0, xv.y + a1);
                ss += a0 * a0 + a1 * a1;
            }
    float t = block_sum256(ss, sm8);
    if (threadIdx.x == 0) atomicAdd(&g_acc[2], t);
}

// mlp1: positive counts, sumsq_relu, gelu via MUFU sigmoid form -> bf16 h
#define L2E2 2.885390081777927f   // 2*log2(e)
__global__ void __launch_bounds__(256, 2) k_mlp1() {
    extern __shared__ char dsm[];
    float* sm8 = (float*)(dsm + 98304);
    int* scnt = (int*)(dsm + 98368);
    if (threadIdx.x < 128) scnt[threadIdx.x] = 0;
    float acc[2][8][4];
    gemm_core(g_xmod, g_w1c, Hc, MLPc, blockIdx.y * 128, blockIdx.x * 128, dsm, acc);
    GEMM_EPI_COORDS
    float ss = 0.f;
    #pragma unroll
    for (int nf = 0; nf < 8; nf++) {
        int cnt0 = 0, cnt1 = 0;
        #pragma unroll
        for (int mf = 0; mf < 2; mf++)
            #pragma unroll
            for (int half = 0; half < 2; half++) {
                float t0 = acc[mf][nf][half*2], t1 = acc[mf][nf][half*2+1];
                ss += t0 * t0 + t1 * t1;
                cnt0 += (t0 > 0.f); cnt1 += (t1 > 0.f);
                float u0 = 0.7978845608028654f * (t0 + 0.044715f * t0 * t0 * t0);
                float u1 = 0.7978845608028654f * (t1 + 0.044715f * t1 * t1 * t1);
                // 0.5*t*(1+tanh(u)) == t*sigmoid(2u) == t/(1+2^(-2u*log2e))
                float g0 = t0 / (1.f + exp2f(-L2E2 * u0));
                float g1 = t1 / (1.f + exp2f(-L2E2 * u1));
                int r  = tileM + wm * 32 + mf * 16 + qd + half * 8;
                int cc = tileN + wn * 64 + nf * 8 + c2;
                *(uint32_t*)&g_h[(size_t)r * MLPc + cc] = pack_bf162(g0, g1);
            }
        atomicAdd(&scnt[wn * 64 + nf * 8 + c2], cnt0);
        atomicAdd(&scnt[wn * 64 + nf * 8 + c2 + 1], cnt1);
    }
    __syncthreads();
    if (threadIdx.x < 128) atomicAdd(&g_pos[tileN + threadIdx.x], scnt[threadIdx.x]);
    float t = block_sum256(ss, sm8);
    if (threadIdx.x == 0) atomicAdd(&g_acc[4], t);
}

// mlp2: out = x_res + gate_mlp*acc ; sumsq_mlp
__global__ void __launch_bounds__(256, 2) k_mlp2(float* __restrict__ out) {
    extern __shared__ char dsm[];
    float* sm8 = (float*)(dsm + 98304);
    float acc[2][8][4];
    gemm_core(g_h, g_w2c, MLPc, Hc, blockIdx.y * 128, blockIdx.x * 128, dsm, acc);
    GEMM_EPI_COORDS
    float ss = 0.f;
    #pragma unroll
    for (int mf = 0; mf < 2; mf++)
        #pragma unroll
        for (int nf = 0; nf < 8; nf++)
            #pragma unroll
            for (int half = 0; half < 2; half++) {
                int r  = tileM + wm * 32 + mf * 16 + qd + half * 8;
                int cc = tileN + wn * 64 + nf * 8 + c2;
                int b = r >> 10;
                size_t idx = (size_t)r * Hc + cc;
                float2 g2 = *(const float2*)&g_cm[b * 6 * Hc + 5 * Hc + cc];
                float2 xr = *(const float2*)&g_xres[idx];
                float m0 = g2.x * acc[mf][nf][half*2];
                float m1 = g2.y * acc[mf][nf][half*2+1];
                *(float2*)&out[idx] = make_float2(xr.x + m0, xr.y + m1);
                ss += m0 * m0 + m1 * m1;
            }
    float t = block_sum256(ss, sm8);
    if (threadIdx.x == 0) atomicAdd(&g_acc[5], t);
}

// ---------------- flash attention: 3-stage K/V ring (gemm-style accounting) ----------
// smem: Q @0 (16KB), K @16384 (3x8KB), V @40960 (3x8KB), sm8 @65536
#define ATT_SMEM 65600
__global__ void __launch_bounds__(256, 2) k_attn() {
    extern __shared__ char dsm[];
    uint32_t sb = smem_u32(dsm);
    uint32_t Qs = sb, Ks = sb + 16384, Vs = sb + 40960;
    float* sm8 = (float*)(dsm + 65536);
    const int tid = threadIdx.x, lane = tid & 31, w = tid >> 5;
    const int g = lane >> 3, lr = lane & 7;
    const int bh = blockIdx.y, qt = blockIdx.x;
    const int nkt = Sc / 64;

    const bf16* Qg = g_q + ((size_t)bh * Sc + qt * 128) * DHc;
    const bf16* Kg = g_k + (size_t)bh * Sc * DHc;
    const bf16* Vg = g_v + (size_t)bh * Sc * DHc;

    // group 0: Q + K/V stage 0 ; group 1: K/V stage 1
    #pragma unroll
    for (int t = 0; t < 4; t++) {
        int ch = tid + t * 256;
        int row = ch >> 3, c = ch & 7;
        cp_async16(sw_addr(Qs, row, c), Qg + (size_t)row * DHc + c * 8);
    }
    #pragma unroll
    for (int t = 0; t < 2; t++) {
        int ch = tid + t * 256;
        int row = ch >> 3, c = ch & 7;
        cp_async16(sw_addr(Ks, row, c), Kg + (size_t)row * DHc + c * 8);
        cp_async16(sw_addr(Vs, row, c), Vg + (size_t)row * DHc + c * 8);
    }
    CP_COMMIT;
    #pragma unroll
    for (int t = 0; t < 2; t++) {
        int ch = tid + t * 256;
        int row = ch >> 3, c = ch & 7;
        cp_async16(sw_addr(Ks + 8192, row, c), Kg + (size_t)(64 + row) * DHc + c * 8);
        cp_async16(sw_addr(Vs + 8192, row, c), Vg + (size_t)(64 + row) * DHc + c * 8);
    }
    CP_COMMIT;

    uint32_t qa[4][4];
    float O[8][4];
    #pragma unroll
    for (int nf = 0; nf < 8; nf++)
        #pragma unroll
        for (int i = 0; i < 4; i++) O[nf][i] = 0.f;
    float m0 = -1e30f, m1 = -1e30f, l0 = 0.f, l1 = 0.f;

    for (int kt = 0; kt < nkt; kt++) {
        CP_WAIT1;
        __syncthreads();
        if (kt == 0) {
            #pragma unroll
            for (int kk = 0; kk < 4; kk++)
                ldsm4(qa[kk], sw_addr(Qs, w * 16 + (g & 1) * 8 + lr, kk * 2 + (g >> 1)));
        }
        uint32_t kb = Ks + (kt % 3) * 8192;
        uint32_t vb = Vs + (kt % 3) * 8192;

        float L[8][4];
        #pragma unroll
        for (int nf = 0; nf < 8; nf++)
            #pragma unroll
            for (int i = 0; i < 4; i++) L[nf][i] = 0.f;
        #pragma unroll
        for (int kk = 0; kk < 4; kk++) {
            #pragma unroll
            for (int p = 0; p < 4; p++) {
                uint32_t b[4];
                ldsm4(b, sw_addr(kb, p * 16 + (g & 1) * 8 + lr, kk * 2 + (g >> 1)));
                mma16816(L[2*p],   qa[kk], b[0], b[2]);
                mma16816(L[2*p+1], qa[kk], b[1], b[3]);
            }
        }
        // online softmax in base 2 (scores pre-scaled by log2e)
        float tm0 = -1e30f, tm1 = -1e30f;
        #pragma unroll
        for (int nf = 0; nf < 8; nf++) {
            tm0 = fmaxf(tm0, fmaxf(L[nf][0], L[nf][1]));
            tm1 = fmaxf(tm1, fmaxf(L[nf][2], L[nf][3]));
        }
        tm0 = fmaxf(tm0, __shfl_xor_sync(0xffffffffu, tm0, 1));
        tm0 = fmaxf(tm0, __shfl_xor_sync(0xffffffffu, tm0, 2));
        tm1 = fmaxf(tm1, __shfl_xor_sync(0xffffffffu, tm1, 1));
        tm1 = fmaxf(tm1, __shfl_xor_sync(0xffffffffu, tm1, 2));
        float mn0 = fmaxf(m0, tm0), mn1 = fmaxf(m1, tm1);
        float cor0 = exp2f(m0 - mn0), cor1 = exp2f(m1 - mn1);
        float s0 = 0.f, s1 = 0.f;
        #pragma unroll
        for (int nf = 0; nf < 8; nf++) {
            L[nf][0] = exp2f(L[nf][0] - mn0);
            L[nf][1] = exp2f(L[nf][1] - mn0);
            L[nf][2] = exp2f(L[nf][2] - mn1);
            L[nf][3] = exp2f(L[nf][3] - mn1);
            s0 += L[nf][0] + L[nf][1];
            s1 += L[nf][2] + L[nf][3];
        }
        s0 += __shfl_xor_sync(0xffffffffu, s0, 1);
        s0 += __shfl_xor_sync(0xffffffffu, s0, 2);
        s1 += __shfl_xor_sync(0xffffffffu, s1, 1);
        s1 += __shfl_xor_sync(0xffffffffu, s1, 2);
        l0 = l0 * cor0 + s0; l1 = l1 * cor1 + s1;
        m0 = mn0; m1 = mn1;
        #pragma unroll
        for (int nf = 0; nf < 8; nf++) {
            O[nf][0] *= cor0; O[nf][1] *= cor0;
            O[nf][2] *= cor1; O[nf][3] *= cor1;
        }
        uint32_t pa[4][4];
        #pragma unroll
        for (int kk = 0; kk < 4; kk++) {
            pa[kk][0] = pack_bf162(L[2*kk][0],   L[2*kk][1]);
            pa[kk][1] = pack_bf162(L[2*kk][2],   L[2*kk][3]);
            pa[kk][2] = pack_bf162(L[2*kk+1][0], L[2*kk+1][1]);
            pa[kk][3] = pack_bf162(L[2*kk+1][2], L[2*kk+1][3]);
        }
        #pragma unroll
        for (int kk = 0; kk < 4; kk++) {
            #pragma unroll
            for (int p = 0; p < 4; p++) {
                uint32_t b[4];
                ldsm4t(b, sw_addr(vb, kk * 16 + (g & 1) * 8 + lr, p * 2 + (g >> 1)));
                mma16816(O[2*p],   pa[kk], b[0], b[1]);
                mma16816(O[2*p+1], pa[kk], b[2], b[3]);
            }
        }
        // prefetch stage kt+2 (buffer (kt+2)%3 == (kt-1)%3, freed by top barrier)
        if (kt + 2 < nkt) {
            int st = (kt + 2) % 3;
            const bf16* Kn = Kg + (size_t)(kt + 2) * 64 * DHc;
            const bf16* Vn = Vg + (size_t)(kt + 2) * 64 * DHc;
            #pragma unroll
            for (int t = 0; t < 2; t++) {
                int ch = tid + t * 256;
                int row = ch >> 3, c = ch & 7;
                cp_async16(sw_addr(Ks + st * 8192, row, c), Kn + (size_t)row * DHc + c * 8);
                cp_async16(sw_addr(Vs + st * 8192, row, c), Vn + (size_t)row * DHc + c * 8);
            }
        }
        CP_COMMIT;
    }
    const int qd = lane >> 2, c2 = (lane & 3) << 1;
    float i0 = 1.f / l0, i1 = 1.f / l1;
    int b = bh >> 4, hh = bh & 15;
    int r0 = qt * 128 + w * 16 + qd;
    #pragma unroll
    for (int nf = 0; nf < 8; nf++) {
        size_t base0 = ((size_t)b * Sc + r0)     * Hc + hh * 64 + nf * 8 + c2;
        size_t base1 = ((size_t)b * Sc + r0 + 8) * Hc + hh * 64 + nf * 8 + c2;
        *(uint32_t*)&g_y[base0] = pack_bf162(O[nf][0] * i0, O[nf][1] * i0);
        *(uint32_t*)&g_y[base1] = pack_bf162(O[nf][2] * i1, O[nf][3] * i1);
    }
    float contrib = ((lane & 3) == 0) ? (i0 + i1) : 0.f;
    float t = block_sum256(contrib, sm8);
    if (tid == 0) atomicAdd(&g_acc[1], t);
}

// ---------------- finalize scalars ----------------
__global__ void k_fin(float* __restrict__ out, int out_size) {
    __shared__ float sm8[8];
    int tid = threadIdx.x;
    float dsum = 0.f; int zc = 0, pc = 0;
    for (int j = tid; j < MLPc; j += 256) {
        int c = g_pos[j];
        float fp = c * (1.f / 8192.f);
        dsum += fabsf(fp - 0.5f);
        zc += (c == 0);
        pc += (c == 8192);
    }
    float d = block_sum256(dsum, sm8);
    float z = block_sum256((float)zc, sm8);
    float p = block_sum256((float)pc, sm8);
    if (tid == 0 && out_size != MROWS * Hc) {
        float* o = out + (out_size - 7);
        o[0] = d * (1.f / 4096.f);
        o[1] = z * (1.f / 4096.f);
        o[2] = p * (1.f / 4096.f);
        o[3] = g_acc[1] * (1.f / 131072.f);
        o[4] = sqrtf(g_acc[2] / g_acc[0]);
        o[5] = sqrtf(g_acc[5] / g_acc[3]);
        o[6] = sqrtf(g_acc[4] / (8192.f * 4096.f));
    }
}

// ---------------- launch ----------------
extern "C" void kernel_launch(void* const* d_in, const int* in_sizes, int n_in,
                              void* d_out, int out_size) {
    const float* x      = (const float*)d_in[0];
    const float* c      = (const float*)d_in[1];
    const float* w_cond = (const float*)d_in[2];
    const float* w_qkv  = (const float*)d_in[3];
    const float* w_attn = (const float*)d_in[4];
    const float* w_mlp1 = (const float*)d_in[5];
    const float* w_mlp2 = (const float*)d_in[6];
    float* out = (float*)d_out;

    cudaFuncSetAttribute(k_qkv,     cudaFuncAttributeMaxDynamicSharedMemorySize, SMEM_G);
    cudaFuncSetAttribute(k_attnout, cudaFuncAttributeMaxDynamicSharedMemorySize, SMEM_G);
    cudaFuncSetAttribute(k_mlp1,    cudaFuncAttributeMaxDynamicSharedMemorySize, SMEM_G);
    cudaFuncSetAttribute(k_mlp2,    cudaFuncAttributeMaxDynamicSharedMemorySize, SMEM_G);
    cudaFuncSetAttribute(k_attn,    cudaFuncAttributeMaxDynamicSharedMemorySize, ATT_SMEM);

    k_prep<<<12480, 256>>>(w_qkv, w_attn, w_mlp1, w_mlp2);
    k_cond<<<dim3(24, 8), 256>>>(c, w_cond);
    k_ln_w<<<MROWS / 8, 256>>>(x, 0, 0, 1, 0);
    k_qkv<<<dim3(24, 64), 256, SMEM_G>>>();
    k_attn<<<dim3(8, Bc * NHc), 256, ATT_SMEM>>>();
    k_attnout<<<dim3(8, 64), 256, SMEM_G>>>(x);
    k_ln_w<<<MROWS / 8, 256>>>(x, 1, 3, 4, 3);
    k_mlp1<<<dim3(32, 64), 256, SMEM_G>>>();
    k_mlp2<<<dim3(8, 64), 256, SMEM_G>>>(out);
    k_fin<<<1, 256>>>(out, out_size);
}